// round 14
// baseline (speedup 1.0000x reference)
#include <cuda_runtime.h>
#include <stdint.h>

#define IMH 1024
#define IMW 1024
#define NB  8
#define WPR 32   // 32-bit words per image row

// Bit-packed strong/weak planes (static device scratch, no allocs)
__device__ uint32_t g_strong[NB * IMH * WPR];
__device__ uint32_t g_weak[NB * IMH * WPR];

#define ROWSF 32    // output rows per warp-task
#define STRIPW 128  // output cols per warp-task (4 cols/lane)

// ---------------------------------------------------------------------------
// K1: barrier-free warp-autonomous pipeline. Each warp owns a 128x32 strip.
// Register rings (3 rows) for raw/bl/mag; horizontal neighbors via shuffles;
// lane 0/31 carry the strip-edge halo locally (extra raw quad -> 2 halo bl
// scalars -> 1 halo mag scalar). No smem, no __syncthreads.
// Body at row r: commit raw(r+3), prefetch raw(r+4), blur row r+2,
// sobel+bin row r+1, NMS+pack row r. 39 bodies (r = y0-7 .. y0+31).
// All FP expressions verbatim from the passing round-13 kernel.
// ---------------------------------------------------------------------------
__global__ void __launch_bounds__(256, 2) canny_front(const float* __restrict__ in)
{
    const int lane = threadIdx.x & 31;
    const int wid  = threadIdx.x >> 5;
    const int task = blockIdx.x * 8 + wid;        // 0..2047
    const int strip = task & 7;
    const int tile  = (task >> 3) & 31;
    const int b     = task >> 8;
    const int c0 = strip * STRIPW;
    const int y0 = tile * ROWSF;
    const bool isL = (lane == 0);
    const bool isR = (lane == 31);
    const bool isEdge = isL || isR;
    const bool exok = isL ? (c0 > 0) : (c0 + STRIPW < IMW);
    const float* img  = in + (size_t)b * IMH * IMW;
    const float* pmain = img + c0 + 4 * lane;
    const float* pex   = img + (isL ? (c0 - 4) : (c0 + STRIPW));

    const float4 Z4 = make_float4(0.f, 0.f, 0.f, 0.f);
    float4 Q[3], QX[3], B[3], M[3];
    float  QL[3], QR[3], BL[3], BR[3], ML[3], MR[3], MX[3];
    float2 BX[3];
    #pragma unroll
    for (int s = 0; s < 3; s++) {
        Q[s] = Z4; QX[s] = Z4; B[s] = Z4; M[s] = Z4;
        QL[s] = QR[s] = BL[s] = BR[s] = ML[s] = MR[s] = MX[s] = 0.f;
        BX[s] = make_float2(0.f, 0.f);
    }
    unsigned binprev = 0u;

    int r = y0 - 7;
    float4 rv = Z4, rvx = Z4;
    {
        int rn = r + 3;
        if ((unsigned)rn < IMH) {
            rv = *(const float4*)(pmain + (size_t)rn * IMW);
            if (isEdge && exok) rvx = *(const float4*)(pex + (size_t)rn * IMW);
        }
    }

#define BODY(K, KO, KM) do {                                                     \
    /* ---- commit raw row r+3 into slot K ---- */                               \
    {   float lft = __shfl_up_sync(0xffffffffu, rv.w, 1);                        \
        float rgt = __shfl_down_sync(0xffffffffu, rv.x, 1);                      \
        if (isL) lft = rvx.w;                                                    \
        if (isR) rgt = rvx.x;                                                    \
        Q[K] = rv; QX[K] = rvx; QL[K] = lft; QR[K] = rgt; }                      \
    /* ---- prefetch raw row r+4 ---- */                                         \
    {   int rn = r + 4;                                                          \
        rv = Z4; rvx = Z4;                                                       \
        if ((unsigned)rn < IMH) {                                                \
            rv = *(const float4*)(pmain + (size_t)rn * IMW);                     \
            if (isEdge && exok) rvx = *(const float4*)(pex + (size_t)rn * IMW);  \
        } }                                                                      \
    /* ---- blur row r+2 (verbatim 9-tap) ---- */                                \
    if (r >= y0 - 4) {                                                           \
        bool rok = (unsigned)(r + 2) < IMH;                                      \
        float4 bq;                                                               \
        bq.x = 0.0625f*QL[KO]  + 0.125f*Q[KO].x + 0.0625f*Q[KO].y               \
             + 0.125f *QL[KM]  + 0.25f *Q[KM].x + 0.125f *Q[KM].y               \
             + 0.0625f*QL[K]   + 0.125f*Q[K].x  + 0.0625f*Q[K].y;               \
        bq.y = 0.0625f*Q[KO].x + 0.125f*Q[KO].y + 0.0625f*Q[KO].z               \
             + 0.125f *Q[KM].x + 0.25f *Q[KM].y + 0.125f *Q[KM].z               \
             + 0.0625f*Q[K].x  + 0.125f*Q[K].y  + 0.0625f*Q[K].z;               \
        bq.z = 0.0625f*Q[KO].y + 0.125f*Q[KO].z + 0.0625f*Q[KO].w               \
             + 0.125f *Q[KM].y + 0.25f *Q[KM].z + 0.125f *Q[KM].w               \
             + 0.0625f*Q[K].y  + 0.125f*Q[K].z  + 0.0625f*Q[K].w;               \
        bq.w = 0.0625f*Q[KO].z + 0.125f*Q[KO].w + 0.0625f*QR[KO]                \
             + 0.125f *Q[KM].z + 0.25f *Q[KM].w + 0.125f *QR[KM]                \
             + 0.0625f*Q[K].z  + 0.125f*Q[K].w  + 0.0625f*QR[K];                \
        /* edge-halo bl scalars (lane0: cols c0-2,c0-1; lane31: c0+128,+129) */  \
        float e0U = isL ? QX[KO].y : Q[KO].w,  e1U = isL ? QX[KO].z : QX[KO].x; \
        float e2U = isL ? QX[KO].w : QX[KO].y, e3U = isL ? Q[KO].x  : QX[KO].z; \
        float e0M = isL ? QX[KM].y : Q[KM].w,  e1M = isL ? QX[KM].z : QX[KM].x; \
        float e2M = isL ? QX[KM].w : QX[KM].y, e3M = isL ? Q[KM].x  : QX[KM].z; \
        float e0D = isL ? QX[K].y  : Q[K].w,   e1D = isL ? QX[K].z  : QX[K].x;  \
        float e2D = isL ? QX[K].w  : QX[K].y,  e3D = isL ? Q[K].x   : QX[K].z;  \
        float ebA = 0.0625f*e0U + 0.125f*e1U + 0.0625f*e2U                      \
                  + 0.125f *e0M + 0.25f *e1M + 0.125f *e2M                      \
                  + 0.0625f*e0D + 0.125f*e1D + 0.0625f*e2D;                     \
        float ebB = 0.0625f*e1U + 0.125f*e2U + 0.0625f*e3U                      \
                  + 0.125f *e1M + 0.25f *e2M + 0.125f *e3M                      \
                  + 0.0625f*e1D + 0.125f*e2D + 0.0625f*e3D;                     \
        if (!rok) { bq = Z4; ebA = 0.f; ebB = 0.f; }                            \
        if (!exok) { ebA = 0.f; ebB = 0.f; }                                    \
        float bl_ = __shfl_up_sync(0xffffffffu, bq.w, 1);                       \
        float br_ = __shfl_down_sync(0xffffffffu, bq.x, 1);                     \
        if (isL) bl_ = ebB;                                                     \
        if (isR) br_ = ebA;                                                     \
        B[K] = bq; BX[K] = make_float2(ebA, ebB); BL[K] = bl_; BR[K] = br_;     \
    }                                                                            \
    /* ---- sobel + mag + bin row r+1 (verbatim) ---- */                         \
    unsigned binnew = 0u;                                                        \
    if (r >= y0 - 2) {                                                           \
        bool rok = (unsigned)(r + 1) < IMH;                                      \
        float4 mq;                                                               \
        {   float gx = (B[KO].y - BL[KO]) + 2.0f*(B[KM].y - BL[KM]) + (B[K].y - BL[K]); \
            float gy = (BL[K] - BL[KO]) + 2.0f*(B[K].x - B[KO].x) + (B[K].y - B[KO].y); \
            mq.x = sqrtf(gx*gx + gy*gy);                                        \
            float ax = fabsf(gx), ay = fabsf(gy);                               \
            bool ss = ((__float_as_uint(gx) ^ __float_as_uint(gy)) >> 31) == 0u;\
            int bn = (ay < 0.41421356237309503f*ax) ? 0 :                       \
                     (ay >= 2.414213562373095f *ax) ? 2 : (ss ? 1 : 3);         \
            binnew |= (unsigned)bn; }                                           \
        {   float gx = (B[KO].z - B[KO].x) + 2.0f*(B[KM].z - B[KM].x) + (B[K].z - B[K].x); \
            float gy = (B[K].x - B[KO].x) + 2.0f*(B[K].y - B[KO].y) + (B[K].z - B[KO].z); \
            mq.y = sqrtf(gx*gx + gy*gy);                                        \
            float ax = fabsf(gx), ay = fabsf(gy);                               \
            bool ss = ((__float_as_uint(gx) ^ __float_as_uint(gy)) >> 31) == 0u;\
            int bn = (ay < 0.41421356237309503f*ax) ? 0 :                       \
                     (ay >= 2.414213562373095f *ax) ? 2 : (ss ? 1 : 3);         \
            binnew |= (unsigned)bn << 2; }                                      \
        {   float gx = (B[KO].w - B[KO].y) + 2.0f*(B[KM].w - B[KM].y) + (B[K].w - B[K].y); \
            float gy = (B[K].y - B[KO].y) + 2.0f*(B[K].z - B[KO].z) + (B[K].w - B[KO].w); \
            mq.z = sqrtf(gx*gx + gy*gy);                                        \
            float ax = fabsf(gx), ay = fabsf(gy);                               \
            bool ss = ((__float_as_uint(gx) ^ __float_as_uint(gy)) >> 31) == 0u;\
            int bn = (ay < 0.41421356237309503f*ax) ? 0 :                       \
                     (ay >= 2.414213562373095f *ax) ? 2 : (ss ? 1 : 3);         \
            binnew |= (unsigned)bn << 4; }                                      \
        {   float gx = (BR[KO] - B[KO].z) + 2.0f*(BR[KM] - B[KM].z) + (BR[K] - B[K].z); \
            float gy = (B[K].z - B[KO].z) + 2.0f*(B[K].w - B[KO].w) + (BR[K] - BR[KO]); \
            mq.w = sqrtf(gx*gx + gy*gy);                                        \
            float ax = fabsf(gx), ay = fabsf(gy);                               \
            bool ss = ((__float_as_uint(gx) ^ __float_as_uint(gy)) >> 31) == 0u;\
            int bn = (ay < 0.41421356237309503f*ax) ? 0 :                       \
                     (ay >= 2.414213562373095f *ax) ? 2 : (ss ? 1 : 3);         \
            binnew |= (unsigned)bn << 6; }                                      \
        /* edge-halo mag scalar (lane0: col c0-1; lane31: col c0+128) */        \
        float f0U = isL ? BX[KO].x : B[KO].w, f1U = isL ? BX[KO].y : BX[KO].x,  \
              f2U = isL ? B[KO].x  : BX[KO].y;                                  \
        float f0M = isL ? BX[KM].x : B[KM].w, f1M = isL ? BX[KM].y : BX[KM].x,  \
              f2M = isL ? B[KM].x  : BX[KM].y;                                  \
        float f0D = isL ? BX[K].x  : B[K].w,  f1D = isL ? BX[K].y  : BX[K].x,   \
              f2D = isL ? B[K].x   : BX[K].y;                                   \
        float gxe = (f2U - f0U) + 2.0f*(f2M - f0M) + (f2D - f0D);               \
        float gye = (f0D - f0U) + 2.0f*(f1D - f1U) + (f2D - f2U);               \
        float mxe = sqrtf(gxe*gxe + gye*gye);                                   \
        if (!rok) { mq = Z4; mxe = 0.f; }                                       \
        if (!exok) mxe = 0.f;                                                   \
        float ml_ = __shfl_up_sync(0xffffffffu, mq.w, 1);                       \
        float mr_ = __shfl_down_sync(0xffffffffu, mq.x, 1);                     \
        if (isL) ml_ = mxe;                                                     \
        if (isR) mr_ = mxe;                                                     \
        M[K] = mq; MX[K] = mxe; ML[K] = ml_; MR[K] = mr_;                       \
    }                                                                            \
    /* ---- NMS + threshold + pack row r (verbatim selection) ---- */            \
    if (r >= y0) {                                                               \
        unsigned vs = 0u, vw = 0u;                                               \
        {   float m = M[KM].x; int bin = (int)(binprev & 3u);                    \
            float n1 = bin==0 ? M[KM].y : (bin==1 ? M[KO].y : (bin==2 ? M[KO].x : ML[KO])); \
            float n2 = bin==0 ? ML[KM]  : (bin==1 ? ML[K]   : (bin==2 ? M[K].x  : M[K].y)); \
            float sup = (m >= n1 && m >= n2) ? m : 0.f;                          \
            if (sup >= 0.3f) vs |= 1u;                                           \
            if (sup >= 0.1f && sup < 0.3f) vw |= 1u; }                           \
        {   float m = M[KM].y; int bin = (int)((binprev >> 2) & 3u);             \
            float n1 = bin==0 ? M[KM].z : (bin==1 ? M[KO].z : (bin==2 ? M[KO].y : M[KO].x)); \
            float n2 = bin==0 ? M[KM].x : (bin==1 ? M[K].x  : (bin==2 ? M[K].y  : M[K].z)); \
            float sup = (m >= n1 && m >= n2) ? m : 0.f;                          \
            if (sup >= 0.3f) vs |= 2u;                                           \
            if (sup >= 0.1f && sup < 0.3f) vw |= 2u; }                           \
        {   float m = M[KM].z; int bin = (int)((binprev >> 4) & 3u);             \
            float n1 = bin==0 ? M[KM].w : (bin==1 ? M[KO].w : (bin==2 ? M[KO].z : M[KO].y)); \
            float n2 = bin==0 ? M[KM].y : (bin==1 ? M[K].y  : (bin==2 ? M[K].z  : M[K].w)); \
            float sup = (m >= n1 && m >= n2) ? m : 0.f;                          \
            if (sup >= 0.3f) vs |= 4u;                                           \
            if (sup >= 0.1f && sup < 0.3f) vw |= 4u; }                           \
        {   float m = M[KM].w; int bin = (int)((binprev >> 6) & 3u);             \
            float n1 = bin==0 ? MR[KM] : (bin==1 ? MR[KO] : (bin==2 ? M[KO].w : M[KO].z)); \
            float n2 = bin==0 ? M[KM].z : (bin==1 ? M[K].z : (bin==2 ? M[K].w  : MR[K])); \
            float sup = (m >= n1 && m >= n2) ? m : 0.f;                          \
            if (sup >= 0.3f) vs |= 8u;                                           \
            if (sup >= 0.1f && sup < 0.3f) vw |= 8u; }                           \
        unsigned msk = 0xFFu << (lane & 24);                                     \
        int sh = (lane & 7) * 4;                                                 \
        unsigned wsv = __reduce_or_sync(msk, vs << sh);                          \
        unsigned wwv = __reduce_or_sync(msk, vw << sh);                          \
        if ((lane & 7) == 0) {                                                   \
            int idx = (b * IMH + r) * WPR + (c0 >> 5) + (lane >> 3);             \
            g_strong[idx] = wsv; g_weak[idx] = wwv;                              \
        }                                                                        \
    }                                                                            \
    binprev = binnew;                                                            \
    r++;                                                                         \
} while (0)

    #pragma unroll 1
    for (int it = 0; it < 13; ++it) {
        BODY(0, 1, 2);
        BODY(1, 2, 0);
        BODY(2, 0, 1);
    }
#undef BODY
}

// ---------------------------------------------------------------------------
// K2: 16 hysteresis iterations, rows in registers (8/warp), horizontal word
// neighbors via shuffles, vertical strip-boundary rows via tiny double-
// buffered smem exchange. One barrier per iteration. Tile = 64 data rows
// (16 halo + 32 interior + 16 halo), full 1024 width; grid 32x8 = 256 blocks.
// Float expansion via 16-entry float4 LUT in smem.
// ---------------------------------------------------------------------------
__global__ void __launch_bounds__(256) canny_hyst(float* __restrict__ out)
{
    __shared__ uint32_t sm_top[2][8][32];
    __shared__ uint32_t sm_bot[2][8][32];
    __shared__ uint32_t Efin[32][32];
    __shared__ float4   lut4[16];

    const int tid  = threadIdx.x;
    const int lane = tid & 31;
    const int w    = tid >> 5;
    const int by   = blockIdx.x;
    const int b    = blockIdx.y;
    const int r0   = by * 32;

    if (tid < 16) {
        lut4[tid] = make_float4((float)(tid & 1), (float)((tid >> 1) & 1),
                                (float)((tid >> 2) & 1), (float)((tid >> 3) & 1));
    }

    uint32_t e[8], wk[8];
    #pragma unroll
    for (int k = 0; k < 8; k++) {
        int gr = r0 - 16 + 8 * w + k;
        uint32_t ev = 0u, wv = 0u;
        if ((unsigned)gr < IMH) {
            int idx = (b * IMH + gr) * WPR + lane;
            ev = g_strong[idx];
            wv = g_weak[idx];
        }
        e[k] = ev; wk[k] = wv;
    }

    #pragma unroll 2
    for (int it = 0; it < 16; ++it) {
        const int p = it & 1;
        sm_top[p][w][lane] = e[0];
        sm_bot[p][w][lane] = e[7];
        __syncthreads();
        uint32_t above = (w > 0) ? sm_bot[p][w - 1][lane] : 0u;
        uint32_t below = (w < 7) ? sm_top[p][w + 1][lane] : 0u;

        uint32_t rowv[10];
        rowv[0] = above;
        #pragma unroll
        for (int k = 0; k < 8; k++) rowv[k + 1] = e[k];
        rowv[9] = below;

        uint32_t h[10];
        #pragma unroll
        for (int k = 0; k < 10; k++) {
            uint32_t m = rowv[k];
            uint32_t l  = __shfl_up_sync(0xffffffffu, m, 1);
            uint32_t rr = __shfl_down_sync(0xffffffffu, m, 1);
            if (lane == 0)  l = 0u;
            if (lane == 31) rr = 0u;
            h[k] = m | (m << 1) | (m >> 1) | (l >> 31) | (rr << 31);
        }
        #pragma unroll
        for (int k = 0; k < 8; k++)
            e[k] = e[k] | (wk[k] & (h[k] | h[k + 1] | h[k + 2]));
    }

    #pragma unroll
    for (int k = 0; k < 8; k++) {
        int dr = 8 * w + k;
        if (dr >= 16 && dr < 48) Efin[dr - 16][lane] = e[k];
    }
    __syncthreads();

    float4* o = (float4*)(out + (size_t)b * IMH * IMW + (size_t)r0 * IMW);
    #pragma unroll
    for (int u = tid; u < 32 * 256; u += 256) {
        int row = u >> 8;
        int q   = u & 255;
        int colpx = q << 2;
        uint32_t word = Efin[row][colpx >> 5];
        o[(row << 8) + q] = lut4[(word >> (colpx & 31)) & 15u];
    }
}

extern "C" void kernel_launch(void* const* d_in, const int* in_sizes, int n_in,
                              void* d_out, int out_size)
{
    const float* in = (const float*)d_in[0];
    float* out = (float*)d_out;

    canny_front<<<256, 256>>>(in);   // 2048 warp-tasks, 8/block

    dim3 g2(32, NB);                 // 256 blocks
    canny_hyst<<<g2, 256>>>(out);
}

// round 15
// speedup vs baseline: 1.0536x; 1.0536x over previous
#include <cuda_runtime.h>
#include <stdint.h>

#define IMH 1024
#define IMW 1024
#define NB  8
#define WPR 32   // 32-bit words per image row

// Bit-packed strong/weak planes (static device scratch, no allocs)
__device__ uint32_t g_strong[NB * IMH * WPR];
__device__ uint32_t g_weak[NB * IMH * WPR];

#define ROWS1 16   // output rows per canny_front block -> 512 blocks

// ---------------------------------------------------------------------------
// K1: single-row rolling pipeline (round-4 proven skeleton + math), but
// 256 threads x 4 cols/thread: fewer LDS per pixel (6-tap loads serve 4
// outputs), STS.128 stores, 8-warp barriers, 49.5KB smem -> 4 blocks/SM.
// Arrays: 1032 floats/row; global col g <-> idx g+4; zero guards at idx 3
// (col -1) and idx 1028 (col 1024). Depth-4 rings, one sync/iteration.
// Pipeline at iter r: store raw(r), bl(r-2), mag(r-4); sync;
// compute bl(r-1), mag+bin(r-3), NMS+threshold+pack row(r-5).
// Overwrite safety: slot re-stored at iter r was last read at iter r-2,
// separated by the iter r-1 sync (same proof as round 4).
// ---------------------------------------------------------------------------
__global__ void __launch_bounds__(256, 4) canny_front(const float* __restrict__ in)
{
    __shared__ __align__(16) float s_raw[4][1032];
    __shared__ __align__(16) float s_bl [4][1032];
    __shared__ __align__(16) float s_mag[4][1032];

    const int t  = threadIdx.x;               // 0..255
    const int b  = blockIdx.y;
    const int y0 = blockIdx.x * ROWS1;
    const float* img = in + (size_t)b * IMH * IMW;
    const int cx = 4 * t;                     // first of 4 owned columns

    // zero guard cells (col -1 -> idx 3, col 1024 -> idx 1028), all 4 slots
    if (t < 4) {
        s_raw[t][3] = 0.f; s_raw[t][1028] = 0.f;
        s_bl [t][3] = 0.f; s_bl [t][1028] = 0.f;
        s_mag[t][3] = 0.f; s_mag[t][1028] = 0.f;
    }

    float4 blp  = make_float4(0.f,0.f,0.f,0.f);   // bl(r-2) pending store
    float4 magp = make_float4(0.f,0.f,0.f,0.f);   // mag(r-4) pending store
    unsigned binm1 = 0u, binm2 = 0u;              // 2-bit bins x 4 cols

    const int r_start = y0 - 3, r_end = y0 + ROWS1 + 4;

    float4 rv = make_float4(0.f,0.f,0.f,0.f);
    if ((unsigned)r_start < IMH)
        rv = *(const float4*)(img + (size_t)r_start * IMW + cx);

    for (int r = r_start; r <= r_end; ++r) {
        // ---- store phase (16B-aligned vector stores) ----
        ((float4*)(s_raw[r & 3]       + 4))[t] = rv;
        ((float4*)(s_bl [(r - 2) & 3] + 4))[t] = blp;
        ((float4*)(s_mag[(r - 4) & 3] + 4))[t] = magp;
        __syncthreads();

        // prefetch raw(r+1)
        float4 rvn = make_float4(0.f,0.f,0.f,0.f);
        if ((unsigned)(r + 1) < IMH)
            rvn = *(const float4*)(img + (size_t)(r + 1) * IMW + cx);

        // ---- blur(r-1): direct 9-tap (verbatim per-output expression) ----
        float4 bln = make_float4(0.f,0.f,0.f,0.f);
        if (r >= y0 - 1 && (unsigned)(r - 1) < IMH) {
            const float* A = s_raw[(r - 2) & 3] + 3 + cx;   // A[0] = col cx-1
            const float* Bm = s_raw[(r - 1) & 3] + 3 + cx;
            const float* C = s_raw[r & 3]        + 3 + cx;
            float a0=A[0],a1=A[1],a2=A[2],a3=A[3],a4=A[4],a5=A[5];
            float m0=Bm[0],m1=Bm[1],m2=Bm[2],m3=Bm[3],m4=Bm[4],m5=Bm[5];
            float d0=C[0],d1=C[1],d2=C[2],d3=C[3],d4=C[4],d5=C[5];
            bln.x = 0.0625f*a0 + 0.125f*a1 + 0.0625f*a2
                  + 0.125f *m0 + 0.25f *m1 + 0.125f *m2
                  + 0.0625f*d0 + 0.125f*d1 + 0.0625f*d2;
            bln.y = 0.0625f*a1 + 0.125f*a2 + 0.0625f*a3
                  + 0.125f *m1 + 0.25f *m2 + 0.125f *m3
                  + 0.0625f*d1 + 0.125f*d2 + 0.0625f*d3;
            bln.z = 0.0625f*a2 + 0.125f*a3 + 0.0625f*a4
                  + 0.125f *m2 + 0.25f *m3 + 0.125f *m4
                  + 0.0625f*d2 + 0.125f*d3 + 0.0625f*d4;
            bln.w = 0.0625f*a3 + 0.125f*a4 + 0.0625f*a5
                  + 0.125f *m3 + 0.25f *m4 + 0.125f *m5
                  + 0.0625f*d3 + 0.125f*d4 + 0.0625f*d5;
        }

        // ---- sobel + mag + bin at row r-3 (verbatim expressions) ----
        float magn[4] = {0.f,0.f,0.f,0.f};
        unsigned binn = 0u;
        if (r >= y0 + 2 && (unsigned)(r - 3) < IMH) {
            const float* U = s_bl[(r - 4) & 3] + 3 + cx;
            const float* Cc = s_bl[(r - 3) & 3] + 3 + cx;
            const float* D = s_bl[(r - 2) & 3] + 3 + cx;
            float u0=U[0],u1=U[1],u2=U[2],u3=U[3],u4=U[4],u5=U[5];
            float c0=Cc[0],c1=Cc[1],c2=Cc[2],c3=Cc[3],c4=Cc[4],c5=Cc[5];
            float d0=D[0],d1=D[1],d2=D[2],d3=D[3],d4=D[4],d5=D[5];
            float uu[6] = {u0,u1,u2,u3,u4,u5};
            float cc[6] = {c0,c1,c2,c3,c4,c5};
            float dd[6] = {d0,d1,d2,d3,d4,d5};
            #pragma unroll
            for (int j = 0; j < 4; j++) {
                float gx = (uu[j+2] - uu[j]) + 2.0f * (cc[j+2] - cc[j]) + (dd[j+2] - dd[j]);
                float gy = (dd[j] - uu[j]) + 2.0f * (dd[j+1] - uu[j+1]) + (dd[j+2] - uu[j+2]);
                magn[j] = sqrtf(gx * gx + gy * gy);
                float ax = fabsf(gx), ay = fabsf(gy);
                bool ss = ((__float_as_uint(gx) ^ __float_as_uint(gy)) >> 31) == 0u;
                int bn = (ay < 0.41421356237309503f * ax) ? 0 :
                         (ay >= 2.414213562373095f  * ax) ? 2 : (ss ? 1 : 3);
                binn |= (unsigned)bn << (2 * j);
            }
        }

        // ---- NMS + double threshold + bitpack at row r-5 ----
        if (r >= y0 + 5) {
            const float* mU = s_mag[(r - 6) & 3] + 4 + cx;   // mU[0] = col cx
            const float* mC = s_mag[(r - 5) & 3] + 4 + cx;
            const float* mD = s_mag[(r - 4) & 3] + 4 + cx;
            unsigned vs = 0u, vw = 0u;
            #pragma unroll
            for (int j = 0; j < 4; j++) {
                float m = mC[j];
                int bin = (int)((binm2 >> (2 * j)) & 3u);
                int dc = (bin <= 1) ? 1 : ((bin == 2) ? 0 : -1);
                const float* p1 = (bin == 0) ? mC : mU;
                const float* p2 = (bin == 0) ? mC : mD;
                float n1 = p1[j + dc], n2 = p2[j - dc];
                float sup = (m >= n1 && m >= n2) ? m : 0.f;
                if (sup >= 0.3f) vs |= (1u << j);
                if (sup >= 0.1f && sup < 0.3f) vw |= (1u << j);
            }
            unsigned msk = 0xFFu << ((t & 31) & 24);   // 8-lane group -> one word
            int sh = 4 * (t & 7);
            unsigned ws = __reduce_or_sync(msk, vs << sh);
            unsigned ww = __reduce_or_sync(msk, vw << sh);
            if ((t & 7) == 0) {
                int idx = (b * IMH + (r - 5)) * WPR + (t >> 3);
                g_strong[idx] = ws;
                g_weak[idx]   = ww;
            }
        }

        // ---- ring shifts ----
        blp = bln;
        magp = make_float4(magn[0], magn[1], magn[2], magn[3]);
        binm2 = binm1; binm1 = binn;
        rv = rvn;
    }
}

// ---------------------------------------------------------------------------
// K2: 16 hysteresis iterations, rows in registers (6/warp), horizontal word
// neighbors via shuffles, vertical strip-boundary rows via tiny double-
// buffered smem exchange. One barrier per iteration. Tile = 48 data rows
// (16 halo + 16 interior + 16 halo), full 1024 width; grid 64x8 = 512 blocks
// for ~2x occupancy vs the 32-interior variant.
// Stale-halo front advances 1 row/iter -> interior exact after 16 iters.
// Float expansion via 16-entry float4 LUT in smem.
// ---------------------------------------------------------------------------
__global__ void __launch_bounds__(256) canny_hyst(float* __restrict__ out)
{
    __shared__ uint32_t sm_top[2][8][32];
    __shared__ uint32_t sm_bot[2][8][32];
    __shared__ uint32_t Efin[16][32];
    __shared__ float4   lut4[16];

    const int tid  = threadIdx.x;
    const int lane = tid & 31;           // word column
    const int w    = tid >> 5;           // warp id 0..7 -> data rows 6w..6w+5
    const int by   = blockIdx.x;         // 0..63
    const int b    = blockIdx.y;
    const int r0   = by * 16;

    if (tid < 16) {
        lut4[tid] = make_float4((float)(tid & 1), (float)((tid >> 1) & 1),
                                (float)((tid >> 2) & 1), (float)((tid >> 3) & 1));
    }

    uint32_t e[6], wk[6];
    #pragma unroll
    for (int k = 0; k < 6; k++) {
        int gr = r0 - 16 + 6 * w + k;
        uint32_t ev = 0u, wv = 0u;
        if ((unsigned)gr < IMH) {
            int idx = (b * IMH + gr) * WPR + lane;
            ev = g_strong[idx];
            wv = g_weak[idx];
        }
        e[k] = ev; wk[k] = wv;
    }

    #pragma unroll 2
    for (int it = 0; it < 16; ++it) {
        const int p = it & 1;
        sm_top[p][w][lane] = e[0];
        sm_bot[p][w][lane] = e[5];
        __syncthreads();
        uint32_t above = (w > 0) ? sm_bot[p][w - 1][lane] : 0u;
        uint32_t below = (w < 7) ? sm_top[p][w + 1][lane] : 0u;

        uint32_t rowv[8];
        rowv[0] = above;
        #pragma unroll
        for (int k = 0; k < 6; k++) rowv[k + 1] = e[k];
        rowv[7] = below;

        uint32_t h[8];
        #pragma unroll
        for (int k = 0; k < 8; k++) {
            uint32_t m = rowv[k];
            uint32_t l  = __shfl_up_sync(0xffffffffu, m, 1);
            uint32_t rr = __shfl_down_sync(0xffffffffu, m, 1);
            if (lane == 0)  l = 0u;
            if (lane == 31) rr = 0u;
            h[k] = m | (m << 1) | (m >> 1) | (l >> 31) | (rr << 31);
        }
        #pragma unroll
        for (int k = 0; k < 6; k++)
            e[k] = e[k] | (wk[k] & (h[k] | h[k + 1] | h[k + 2]));
    }

    // publish interior rows (data rows 16..31 -> global rows r0..r0+15)
    #pragma unroll
    for (int k = 0; k < 6; k++) {
        int dr = 6 * w + k;
        if (dr >= 16 && dr < 32) Efin[dr - 16][lane] = e[k];
    }
    __syncthreads();

    float4* o = (float4*)(out + (size_t)b * IMH * IMW + (size_t)r0 * IMW);
    #pragma unroll
    for (int u = tid; u < 16 * 256; u += 256) {
        int row = u >> 8;                 // 256 float4 per image row
        int q   = u & 255;
        int colpx = q << 2;
        uint32_t word = Efin[row][colpx >> 5];
        o[(row << 8) + q] = lut4[(word >> (colpx & 31)) & 15u];
    }
}

extern "C" void kernel_launch(void* const* d_in, const int* in_sizes, int n_in,
                              void* d_out, int out_size)
{
    const float* in = (const float*)d_in[0];
    float* out = (float*)d_out;

    dim3 g1(IMH / ROWS1, NB);     // 64 x 8 = 512 blocks
    canny_front<<<g1, 256>>>(in);

    dim3 g2(64, NB);              // 64 x 8 = 512 blocks
    canny_hyst<<<g2, 256>>>(out);
}

// round 16
// speedup vs baseline: 1.2597x; 1.1956x over previous
#include <cuda_runtime.h>
#include <stdint.h>

#define IMH 1024
#define IMW 1024
#define NB  8
#define WPR 32   // 32-bit words per image row

// Bit-packed strong/weak planes (static device scratch, no allocs)
__device__ uint32_t g_strong[NB * IMH * WPR];
__device__ uint32_t g_weak[NB * IMH * WPR];

#define ROWS1 32   // output rows per canny_front block

#define HI2 (0.3f * 0.3f)   // squared thresholds (sqrt is monotone)
#define LO2 (0.1f * 0.1f)

// ---- round-4 math, mag kept SQUARED (only used in order comparisons) ----
#define BLUR9(A,B,C,out) do { \
    float t0=(A)[cx],t1=(A)[cx+1],t2=(A)[cx+2],t3=(A)[cx+3]; \
    float m0=(B)[cx],m1=(B)[cx+1],m2=(B)[cx+2],m3=(B)[cx+3]; \
    float d0=(C)[cx],d1=(C)[cx+1],d2=(C)[cx+2],d3=(C)[cx+3]; \
    (out).x = 0.0625f * t0 + 0.125f * t1 + 0.0625f * t2 \
            + 0.125f  * m0 + 0.25f  * m1 + 0.125f  * m2 \
            + 0.0625f * d0 + 0.125f * d1 + 0.0625f * d2; \
    (out).y = 0.0625f * t1 + 0.125f * t2 + 0.0625f * t3 \
            + 0.125f  * m1 + 0.25f  * m2 + 0.125f  * m3 \
            + 0.0625f * d1 + 0.125f * d2 + 0.0625f * d3; \
} while(0)

#define SOBEL(U,C,D,magv,binx,biny) do { \
    float u0=(U)[cx],u1=(U)[cx+1],u2=(U)[cx+2],u3=(U)[cx+3]; \
    float c0=(C)[cx],c1=(C)[cx+1],c2=(C)[cx+2],c3=(C)[cx+3]; \
    float d0=(D)[cx],d1=(D)[cx+1],d2=(D)[cx+2],d3=(D)[cx+3]; \
    { float gx = (u2 - u0) + 2.0f * (c2 - c0) + (d2 - d0); \
      float gy = (d0 - u0) + 2.0f * (d1 - u1) + (d2 - u2); \
      (magv).x = gx * gx + gy * gy; \
      float ax = fabsf(gx), ay = fabsf(gy); \
      bool ss = ((__float_as_uint(gx) ^ __float_as_uint(gy)) >> 31) == 0u; \
      binx = (ay < 0.41421356237309503f * ax) ? 0 : \
             (ay >= 2.414213562373095f  * ax) ? 2 : (ss ? 1 : 3); } \
    { float gx = (u3 - u1) + 2.0f * (c3 - c1) + (d3 - d1); \
      float gy = (d1 - u1) + 2.0f * (d2 - u2) + (d3 - u3); \
      (magv).y = gx * gx + gy * gy; \
      float ax = fabsf(gx), ay = fabsf(gy); \
      bool ss = ((__float_as_uint(gx) ^ __float_as_uint(gy)) >> 31) == 0u; \
      biny = (ay < 0.41421356237309503f * ax) ? 0 : \
             (ay >= 2.414213562373095f  * ax) ? 2 : (ss ? 1 : 3); } \
} while(0)

#define NMSPACK(MU,MC,MD,BINX,BINY,ROWN) do { \
    bool s0,w0,s1,w1; \
    { float m = (MC)[1+cx]; int bin = (BINX); \
      int dc = (bin <= 1) ? 1 : ((bin == 2) ? 0 : -1); \
      const float* p1 = (bin == 0) ? (MC) : (MU); \
      const float* p2 = (bin == 0) ? (MC) : (MD); \
      float n1 = p1[1 + cx + dc], n2 = p2[1 + cx - dc]; \
      float sup = (m >= n1 && m >= n2) ? m : 0.f; \
      s0 = sup >= HI2; w0 = (sup >= LO2) && (sup < HI2); } \
    { float m = (MC)[2+cx]; int bin = (BINY); \
      int dc = (bin <= 1) ? 1 : ((bin == 2) ? 0 : -1); \
      const float* p1 = (bin == 0) ? (MC) : (MU); \
      const float* p2 = (bin == 0) ? (MC) : (MD); \
      float n1 = p1[2 + cx + dc], n2 = p2[2 + cx - dc]; \
      float sup = (m >= n1 && m >= n2) ? m : 0.f; \
      s1 = sup >= HI2; w1 = (sup >= LO2) && (sup < HI2); } \
    unsigned vs = (s0 ? 1u : 0u) | (s1 ? 2u : 0u); \
    unsigned vw = (w0 ? 1u : 0u) | (w1 ? 2u : 0u); \
    unsigned msk = ((tid >> 4) & 1) ? 0xFFFF0000u : 0x0000FFFFu; \
    int sh = 2 * (tid & 15); \
    unsigned ws = __reduce_or_sync(msk, vs << sh); \
    unsigned ww = __reduce_or_sync(msk, vw << sh); \
    if ((tid & 15) == 0) { \
        int idx = (b * IMH + (ROWN)) * WPR + (cx >> 5); \
        g_strong[idx] = ws; g_weak[idx] = ww; } \
} while(0)

// One pair-iteration. S = compile-time slot of row r (slot(n) = (n-(y0-3)) mod 6).
// Stores raw(r),raw(r+1), bl(r-3),bl(r-2), mag(r-6),mag(r-5); sync;
// prefetch raw(r+2,r+3); compute bl(r-1,r), mag+bin(r-4,r-3); NMS rows (r-7,r-6).
// Overwrite hazards: each overwritten row's last reader ran 2 pair-iterations
// earlier, separated by an intervening __syncthreads -> depth-6 rings safe.
#define BODY(S) do { \
    { float* pr0 = s_raw[(S+0)%6]; float* pr1 = s_raw[(S+1)%6]; \
      float* pb0 = s_bl [(S+3)%6]; float* pb1 = s_bl [(S+4)%6]; \
      float* pm0 = s_mag[(S+0)%6]; float* pm1 = s_mag[(S+1)%6]; \
      pr0[1+cx]=rv0.x; pr0[2+cx]=rv0.y; pr1[1+cx]=rv1.x; pr1[2+cx]=rv1.y; \
      pb0[1+cx]=blp0.x; pb0[2+cx]=blp0.y; pb1[1+cx]=blp1.x; pb1[2+cx]=blp1.y; \
      pm0[1+cx]=magp0.x; pm0[2+cx]=magp0.y; pm1[1+cx]=magp1.x; pm1[2+cx]=magp1.y; } \
    __syncthreads(); \
    rv0 = make_float2(0.f,0.f); rv1 = make_float2(0.f,0.f); \
    if ((unsigned)(r+2) < IMH) rv0 = ((const float2*)(img + (size_t)(r+2) * IMW))[tid]; \
    if ((unsigned)(r+3) < IMH) rv1 = ((const float2*)(img + (size_t)(r+3) * IMW))[tid]; \
    { const float* q0 = s_raw[(S+4)%6]; const float* q1 = s_raw[(S+5)%6]; \
      const float* q2 = s_raw[(S+0)%6]; const float* q3 = s_raw[(S+1)%6]; \
      float2 bn0 = make_float2(0.f,0.f), bn1 = make_float2(0.f,0.f); \
      if (r >= y0 - 1 && (unsigned)(r-1) < IMH) BLUR9(q0,q1,q2,bn0); \
      if (r >= y0 - 2 && (unsigned)(r)   < IMH) BLUR9(q1,q2,q3,bn1); \
      blp0 = bn0; blp1 = bn1; } \
    { const float* v0 = s_bl[(S+1)%6]; const float* v1 = s_bl[(S+2)%6]; \
      const float* v2 = s_bl[(S+3)%6]; const float* v3 = s_bl[(S+4)%6]; \
      float2 mg0 = make_float2(0.f,0.f), mg1 = make_float2(0.f,0.f); \
      int bAx=0,bAy=0,bBx=0,bBy=0; \
      if (r >= y0 + 3 && (unsigned)(r-4) < IMH) SOBEL(v0,v1,v2,mg0,bAx,bAy); \
      if (r >= y0 + 2 && (unsigned)(r-3) < IMH) SOBEL(v1,v2,v3,mg1,bBx,bBy); \
      { const float* n0 = s_mag[(S+4)%6]; const float* n1 = s_mag[(S+5)%6]; \
        const float* n2 = s_mag[(S+0)%6]; const float* n3 = s_mag[(S+1)%6]; \
        if (r >= y0 + 7 && r < y0 + ROWS1 + 7) NMSPACK(n0,n1,n2,binB2x,binB2y,(r-7)); \
        if (r >= y0 + 6 && r < y0 + ROWS1 + 6) NMSPACK(n1,n2,n3,binA1x,binA1y,(r-6)); } \
      magp0 = mg0; magp1 = mg1; \
      binB2x = binB1x; binB2y = binB1y; \
      binB1x = bBx; binB1y = bBy; binA1x = bAx; binA1y = bAy; } \
    r += 2; \
} while (0)

// ---------------------------------------------------------------------------
// K1: 2-row-paired rolling pipeline, 512 threads x 2 cols, full-width rows.
// Depth-6 smem rings, one barrier per PAIR of rows. Squared-magnitude NMS
// (no sqrt: monotone transform preserves all comparison outcomes except
// sqrt-rounding collisions).
// ---------------------------------------------------------------------------
__global__ void __launch_bounds__(512, 2) canny_front(const float* __restrict__ in)
{
    __shared__ float s_raw[6][1026];
    __shared__ float s_bl [6][1026];
    __shared__ float s_mag[6][1026];

    const int tid = threadIdx.x;              // 0..511
    const int b   = blockIdx.y;
    const int y0  = blockIdx.x * ROWS1;
    const float* img = in + (size_t)b * IMH * IMW;
    const int cx = tid * 2;                   // columns cx, cx+1

    // zero guard columns (index 0 and 1025), all 6 slots
    if (tid < 12) {
        int s = tid % 6, g = (tid / 6) * 1025;
        s_raw[s][g] = 0.f; s_bl[s][g] = 0.f; s_mag[s][g] = 0.f;
    }

    float2 blp0  = make_float2(0.f,0.f), blp1  = make_float2(0.f,0.f);
    float2 magp0 = make_float2(0.f,0.f), magp1 = make_float2(0.f,0.f);
    int binA1x=0, binA1y=0, binB1x=0, binB1y=0, binB2x=0, binB2y=0;

    int r = y0 - 3;
    float2 rv0 = make_float2(0.f,0.f), rv1 = make_float2(0.f,0.f);
    if ((unsigned)r       < IMH) rv0 = ((const float2*)(img + (size_t)r       * IMW))[tid];
    if ((unsigned)(r + 1) < IMH) rv1 = ((const float2*)(img + (size_t)(r + 1) * IMW))[tid];

    // 21 pair-iterations = 7 x (slots 0,2,4)
    #pragma unroll 1
    for (int jj = 0; jj < 7; ++jj) {
        BODY(0);
        BODY(2);
        BODY(4);
    }
}

// ---------------------------------------------------------------------------
// K2: hysteresis, rows in registers (8/warp), horizontal word neighbors via
// shuffles, vertical strip-boundary rows via double-buffered smem exchange.
// One barrier per iteration (fused with convergence check via
// __syncthreads_or): if an iteration changes nothing, the fixed point is
// reached and the remaining iterations are identity -> exact early exit
// (lagging one iteration). Tile = 64 data rows (16+32+16), grid 32x8.
// Float expansion via 16-entry float4 LUT.
// ---------------------------------------------------------------------------
__global__ void __launch_bounds__(256) canny_hyst(float* __restrict__ out)
{
    __shared__ uint32_t sm_top[2][8][32];
    __shared__ uint32_t sm_bot[2][8][32];
    __shared__ uint32_t Efin[32][32];
    __shared__ float4   lut4[16];

    const int tid  = threadIdx.x;
    const int lane = tid & 31;           // word column
    const int w    = tid >> 5;           // warp id 0..7 -> data rows 8w..8w+7
    const int by   = blockIdx.x;         // 0..31
    const int b    = blockIdx.y;
    const int r0   = by * 32;

    if (tid < 16) {
        lut4[tid] = make_float4((float)(tid & 1), (float)((tid >> 1) & 1),
                                (float)((tid >> 2) & 1), (float)((tid >> 3) & 1));
    }

    uint32_t e[8], wk[8];
    #pragma unroll
    for (int k = 0; k < 8; k++) {
        int gr = r0 - 16 + 8 * w + k;
        uint32_t ev = 0u, wv = 0u;
        if ((unsigned)gr < IMH) {
            int idx = (b * IMH + gr) * WPR + lane;
            ev = g_strong[idx];
            wv = g_weak[idx];
        }
        e[k] = ev; wk[k] = wv;
    }

    unsigned changed = 1u;
    #pragma unroll 1
    for (int it = 0; it < 16; ++it) {
        const int p = it & 1;
        sm_top[p][w][lane] = e[0];
        sm_bot[p][w][lane] = e[7];
        int any = __syncthreads_or((int)(changed != 0u));
        if (!any) break;
        uint32_t above = (w > 0) ? sm_bot[p][w - 1][lane] : 0u;
        uint32_t below = (w < 7) ? sm_top[p][w + 1][lane] : 0u;

        uint32_t rowv[10];
        rowv[0] = above;
        #pragma unroll
        for (int k = 0; k < 8; k++) rowv[k + 1] = e[k];
        rowv[9] = below;

        uint32_t h[10];
        #pragma unroll
        for (int k = 0; k < 10; k++) {
            uint32_t m = rowv[k];
            uint32_t l  = __shfl_up_sync(0xffffffffu, m, 1);
            uint32_t rr = __shfl_down_sync(0xffffffffu, m, 1);
            if (lane == 0)  l = 0u;
            if (lane == 31) rr = 0u;
            h[k] = m | (m << 1) | (m >> 1) | (l >> 31) | (rr << 31);
        }
        changed = 0u;
        #pragma unroll
        for (int k = 0; k < 8; k++) {
            uint32_t ne = e[k] | (wk[k] & (h[k] | h[k + 1] | h[k + 2]));
            changed |= (ne ^ e[k]);
            e[k] = ne;
        }
    }

    // publish interior rows (data rows 16..47 -> global rows r0..r0+31)
    #pragma unroll
    for (int k = 0; k < 8; k++) {
        int dr = 8 * w + k;
        if (dr >= 16 && dr < 48) Efin[dr - 16][lane] = e[k];
    }
    __syncthreads();

    float4* o = (float4*)(out + (size_t)b * IMH * IMW + (size_t)r0 * IMW);
    #pragma unroll
    for (int u = tid; u < 32 * 256; u += 256) {
        int row = u >> 8;                 // 256 float4 per image row
        int q   = u & 255;
        int colpx = q << 2;
        uint32_t word = Efin[row][colpx >> 5];
        o[(row << 8) + q] = lut4[(word >> (colpx & 31)) & 15u];
    }
}

extern "C" void kernel_launch(void* const* d_in, const int* in_sizes, int n_in,
                              void* d_out, int out_size)
{
    const float* in = (const float*)d_in[0];
    float* out = (float*)d_out;

    dim3 g1(IMH / ROWS1, NB);     // 32 x 8 = 256 blocks
    canny_front<<<g1, 512>>>(in);

    dim3 g2(32, NB);              // 32 x 8 = 256 blocks
    canny_hyst<<<g2, 256>>>(out);
}